// round 12
// baseline (speedup 1.0000x reference)
#include <cuda_runtime.h>
#include <cuda_bf16.h>

// Problem constants (fixed dataset: N=50000, E=800000, D=64, H=128)
#define D  64
#define H  128
#define MAXN 50000

#define SA_STRIDE 72     // bf16 elems per row (64 + 8 pad)
#define SH_STRIDE 136    // bf16 elems per row (128 + 8 pad)

// Scratch
__device__ float g_agg[MAXN * D];      // segment_sum target
__device__ float g_P[MAXN * 384];      // [0:128]=nf@We1_s, [128:256]=nf@We1_r, [256:384]=nf@Wn1_n

typedef unsigned int u32;
typedef unsigned long long u64;

extern __shared__ char smem_raw[];

// ---- edge kernel smem map (64-row tiles, 256 threads, 2 CTAs/SM) ----
//  0:      sSS[2][64]   (512B, double-buffered)
//  512:    sSR[2][64]   (512B)
//  1024:   A32 fp32 [64][68]  (17408)  <- cp.async prefetch target
//  18432:  AH bf16 (9216)   | sF fp32 [64][68] overlays AH/AL after mma1
//  27648:  AL bf16 (9216)
//  36864:  HH bf16 (17408)
//  54272:  HL bf16 (17408)
//  71680:  W2H bf16 (17408)
//  89088:  W2L bf16 (17408)   -> total 106496 (x2 CTAs = 212992 <= 228K)
#define EOFF_SS   0
#define EOFF_SR   512
#define EOFF_A32  1024
#define EOFF_AH   18432
#define EOFF_AL   27648
#define EOFF_HH   36864
#define EOFF_HL   54272
#define EOFF_W2H  71680
#define EOFF_W2L  89088
#define EDGE_SMEM 106496

// ---- node/pproj smem map (128-row tiles, 512 threads, 1 CTA/SM) ----
#define BOFF_AH   1024
#define BOFF_AL   19456
#define BOFF_HH   37888
#define BOFF_HL   72704
#define BIG_SMEM  107520
#define PPROJ_SMEM 37888

// ============================================================================
__device__ __forceinline__ u32 smem_u32(const void* p) {
    u32 a; asm("{ .reg .u64 t; cvta.to.shared.u64 t, %1; cvt.u32.u64 %0, t; }" : "=r"(a) : "l"(p));
    return a;
}
__device__ __forceinline__ u32 pack_bf2(float lo, float hi) {
    u32 r; asm("cvt.rn.bf16x2.f32 %0, %1, %2;" : "=r"(r) : "f"(hi), "f"(lo)); return r;
}
__device__ __forceinline__ float lowf(u32 p)  { return __uint_as_float(p << 16); }
__device__ __forceinline__ float highf(u32 p) { return __uint_as_float(p & 0xFFFF0000u); }

__device__ __forceinline__ void ldsm4(u32* r, u32 addr) {
    asm volatile("ldmatrix.sync.aligned.m8n8.x4.shared.b16 {%0,%1,%2,%3}, [%4];"
        : "=r"(r[0]), "=r"(r[1]), "=r"(r[2]), "=r"(r[3]) : "r"(addr));
}
__device__ __forceinline__ void ldsm2(u32* r, u32 addr) {
    asm volatile("ldmatrix.sync.aligned.m8n8.x2.shared.b16 {%0,%1}, [%2];"
        : "=r"(r[0]), "=r"(r[1]) : "r"(addr));
}
__device__ __forceinline__ void mma_bf(float* c, const u32* a, const u32* b) {
    asm volatile("mma.sync.aligned.m16n8k16.row.col.f32.bf16.bf16.f32 "
        "{%0,%1,%2,%3}, {%4,%5,%6,%7}, {%8,%9}, {%0,%1,%2,%3};"
        : "+f"(c[0]), "+f"(c[1]), "+f"(c[2]), "+f"(c[3])
        : "r"(a[0]), "r"(a[1]), "r"(a[2]), "r"(a[3]), "r"(b[0]), "r"(b[1]));
}
__device__ __forceinline__ void build_frag(const float* __restrict__ W, int ldw,
                                           int n, int k0, u32& hi, u32& lo) {
    const float w0 = W[k0 * ldw + n];
    const float w1 = W[(k0 + 1) * ldw + n];
    hi = pack_bf2(w0, w1);
    lo = pack_bf2(w0 - lowf(hi), w1 - highf(hi));
}
__device__ __forceinline__ void stage_row_quarter(char* sm, const float4* src4,
                                                  int row, int q, int offH, int offL) {
#pragma unroll
    for (int j = 0; j < 4; j++) {
        const float4 v = src4[q + 4 * j];
        const int col = (q + 4 * j) * 4;
        const u32 off = (u32)(row * SA_STRIDE + col) * 2;
        const u32 h0 = pack_bf2(v.x, v.y);
        const u32 h1 = pack_bf2(v.z, v.w);
        *(u32*)(sm + offH + off)     = h0;
        *(u32*)(sm + offH + off + 4) = h1;
        *(u32*)(sm + offL + off)     = pack_bf2(v.x - lowf(h0), v.y - highf(h0));
        *(u32*)(sm + offL + off + 4) = pack_bf2(v.z - lowf(h1), v.w - highf(h1));
    }
}
__device__ __forceinline__ void stage_w2t(char* sm, const float* __restrict__ W2, int tid) {
    for (int i = tid; i < 64 * 64; i += 256) {
        const int n = i >> 6, kp = i & 63;
        const float w0 = W2[(2 * kp) * 64 + n];
        const float w1 = W2[(2 * kp + 1) * 64 + n];
        const u32 hi = pack_bf2(w0, w1);
        const u32 lo = pack_bf2(w0 - lowf(hi), w1 - highf(hi));
        const u32 off = (u32)(n * SH_STRIDE + 2 * kp) * 2;
        *(u32*)(sm + EOFF_W2H + off) = hi;
        *(u32*)(sm + EOFF_W2L + off) = lo;
    }
}

// ---- cp.async helpers ----
#define CP_ASYNC16(s, g) asm volatile("cp.async.ca.shared.global [%0], [%1], 16;" :: "r"(s), "l"(g))
#define CP_ASYNC4(s, g)  asm volatile("cp.async.ca.shared.global [%0], [%1], 4;"  :: "r"(s), "l"(g))
#define CP_COMMIT()      asm volatile("cp.async.commit_group;" ::: "memory")
#define CP_WAIT0()       asm volatile("cp.async.wait_group 0;" ::: "memory")

// prefetch one edge tile (indices + raw fp32 features) into smem via cp.async
__device__ __forceinline__ void prefetch_edge_tile(
    u32 smb, const float* __restrict__ edgef,
    const int* __restrict__ senders, const int* __restrict__ recvs,
    int base, int E, int par, int tid)
{
    if (tid < 64) {
        int g = base + tid; if (g >= E) g = E - 1;
        CP_ASYNC4(smb + EOFF_SS + par * 256 + tid * 4, senders + g);
        CP_ASYNC4(smb + EOFF_SR + par * 256 + tid * 4, recvs + g);
    }
    const int row = tid >> 2, q = tid & 3;
    int ge = base + row; if (ge >= E) ge = E - 1;
    const float* src = edgef + (size_t)ge * 64;
#pragma unroll
    for (int j = 0; j < 4; j++) {
        const int c = (q + 4 * j) * 4;
        CP_ASYNC16(smb + EOFF_A32 + (row * 68 + c) * 4, src + c);
    }
    CP_COMMIT();
}

// ============================================================================
// P projection (mma bf16 3-term) + zeroing of g_agg (absorbed zero kernel).
__global__ __launch_bounds__(512)
void pproj_kernel(const float* __restrict__ nodef,
                  const float* __restrict__ We1, const float* __restrict__ Wn1, int N)
{
    char* sm = smem_raw;
    const u32 smb = smem_u32(sm);
    const u32 ahb = smb + BOFF_AH, alb = smb + BOFF_AL;

    const int tid = threadIdx.x, wid = tid >> 5, lid = tid & 31;
    const int nrow = lid >> 2, cq = (lid & 3) * 2;
    const int base = blockIdx.x * 128;

    // zero g_agg rows for this tile (independent of the rest)
    {
        const int lim = (N - base < 128) ? (N - base) : 128;
        float4* dst = (float4*)(g_agg + (size_t)base * 64);
        const int n4 = lim * 16;
        for (int i = tid; i < n4; i += 512) dst[i] = make_float4(0.f, 0.f, 0.f, 0.f);
    }

    u32 bh[3][4][2], bl[3][4][2];
    {
        const int n = wid * 8 + nrow;
#pragma unroll
        for (int kt = 0; kt < 4; kt++)
#pragma unroll
            for (int r = 0; r < 2; r++) {
                const int k = kt * 16 + cq + r * 8;
                build_frag(We1 + (size_t)64 * 128, 128, n, k, bh[0][kt][r], bl[0][kt][r]);
                build_frag(We1 + (size_t)128 * 128, 128, n, k, bh[1][kt][r], bl[1][kt][r]);
                build_frag(Wn1 + (size_t)64 * 128, 128, n, k, bh[2][kt][r], bl[2][kt][r]);
            }
    }
    {
        const int row = tid >> 2, q = tid & 3;
        int g = base + row; if (g >= N) g = N - 1;
        stage_row_quarter(sm, (const float4*)(nodef + (size_t)g * 64), row, q, BOFF_AH, BOFF_AL);
    }
    __syncthreads();

    const int trow = (lid & 7) + ((lid >> 3) & 1) * 8;
    const int tcol = (lid >> 4) * 8;
    const u32 offA = (u32)(trow * SA_STRIDE + tcol) * 2;
    const int n0 = wid * 8 + cq;

#pragma unroll
    for (int mt = 0; mt < 8; mt++) {
        u32 ah[4][4], al[4][4];
        const u32 bhA = ahb + offA + mt * (16 * SA_STRIDE * 2);
        const u32 blA = alb + offA + mt * (16 * SA_STRIDE * 2);
#pragma unroll
        for (int kt = 0; kt < 4; kt++) {
            ldsm4(ah[kt], bhA + kt * 32);
            ldsm4(al[kt], blA + kt * 32);
        }
        const int g0 = base + mt * 16 + nrow, g1 = g0 + 8;
#pragma unroll
        for (int seg = 0; seg < 3; seg++) {
            float acc[4] = {0.f, 0.f, 0.f, 0.f};
#pragma unroll
            for (int kt = 0; kt < 4; kt++) {
                mma_bf(acc, ah[kt], bh[seg][kt]);
                mma_bf(acc, ah[kt], bl[seg][kt]);
                mma_bf(acc, al[kt], bh[seg][kt]);
            }
            if (g0 < N) *(float2*)(g_P + (size_t)g0 * 384 + seg * 128 + n0) =
                            make_float2(acc[0], acc[1]);
            if (g1 < N) *(float2*)(g_P + (size_t)g1 * 384 + seg * 128 + n0) =
                            make_float2(acc[2], acc[3]);
        }
    }
}

// ============================================================================
// Edge kernel: persistent, 256 threads, 2 CTAs/SM, cp.async pipelined A-stage.
__global__ __launch_bounds__(256, 2)
void edge_kernel(const float* __restrict__ edgef,
                 const float* __restrict__ We1, const float* __restrict__ be1,
                 const float* __restrict__ We2, const float* __restrict__ be2,
                 const int* __restrict__ senders, const int* __restrict__ recvs,
                 float* __restrict__ e_out, int E)
{
    char* sm = smem_raw;
    float* sF = (float*)(sm + EOFF_AH);       // epilogue2 fp32 staging [64][68]
    const u32 smb = smem_u32(sm);
    const u32 ahb = smb + EOFF_AH, alb = smb + EOFF_AL;
    const u32 hhb = smb + EOFF_HH, hlb = smb + EOFF_HL;
    const u32 w2h = smb + EOFF_W2H, w2l = smb + EOFF_W2L;

    const int tid = threadIdx.x, wid = tid >> 5, lid = tid & 31;
    const int nrow = lid >> 2, cq = (lid & 3) * 2;

    stage_w2t(sm, We2, tid);

    u32 b1h[2][4][2], b1l[2][4][2];
#pragma unroll
    for (int nt = 0; nt < 2; nt++) {
        const int n = wid * 16 + nt * 8 + nrow;
#pragma unroll
        for (int kt = 0; kt < 4; kt++)
#pragma unroll
            for (int r = 0; r < 2; r++)
                build_frag(We1, 128, n, kt * 16 + cq + r * 8, b1h[nt][kt][r], b1l[nt][kt][r]);
    }
    float2 bb1[2];
    bb1[0] = *(const float2*)(be1 + wid * 16 + cq);
    bb1[1] = *(const float2*)(be1 + wid * 16 + 8 + cq);
    const float2 bb2 = *(const float2*)(be2 + wid * 8 + cq);

    const int trow = (lid & 7) + ((lid >> 3) & 1) * 8;
    const int tcol = (lid >> 4) * 8;
    const u32 offA = (u32)(trow * SA_STRIDE + tcol) * 2;
    const u32 offH = (u32)(trow * SH_STRIDE + tcol) * 2;
    const u32 offB = (u32)((wid * 8 + (lid & 7)) * SH_STRIDE + ((lid >> 3) & 1) * 8) * 2;

    const int nTiles = (E + 63) / 64;
    int par = 0;

    // prologue: prefetch the first tile
    if (blockIdx.x < nTiles)
        prefetch_edge_tile(smb, edgef, senders, recvs, blockIdx.x * 64, E, par, tid);

    for (int tile = blockIdx.x; tile < nTiles; tile += gridDim.x) {
        const int base = tile * 64;

        // wait for this tile's prefetch; previous tile's sF reads also done
        CP_WAIT0();
        __syncthreads();

        // ---- convert A32 (fp32) -> AH/AL (bf16 hi/lo) ----
        {
            const int row = tid >> 2, q = tid & 3;
            stage_row_quarter(sm, (const float4*)(sm + EOFF_A32 + row * 272), row, q,
                              EOFF_AH, EOFF_AL);
        }
        __syncthreads();   // A32 free; AH/AL visible

        // ---- prefetch NEXT tile (hidden under MMA phases) ----
        {
            const int nxt = tile + gridDim.x;
            if (nxt < nTiles)
                prefetch_edge_tile(smb, edgef, senders, recvs, nxt * 64, E, par ^ 1, tid);
        }

        const int* sSS = (const int*)(sm + EOFF_SS + par * 256);
        const int* sSR = (const int*)(sm + EOFF_SR + par * 256);

        // ---- layer 1: acc1[64,128] = A @ We1_e^T (+be1) ----
        float acc1[4][2][4];
#pragma unroll
        for (int mt = 0; mt < 4; mt++)
#pragma unroll
            for (int nt = 0; nt < 2; nt++) {
                acc1[mt][nt][0] = bb1[nt].x; acc1[mt][nt][1] = bb1[nt].y;
                acc1[mt][nt][2] = bb1[nt].x; acc1[mt][nt][3] = bb1[nt].y;
            }
#pragma unroll
        for (int mt = 0; mt < 4; mt++) {
            const u32 bh = ahb + offA + mt * (16 * SA_STRIDE * 2);
            const u32 bl = alb + offA + mt * (16 * SA_STRIDE * 2);
#pragma unroll
            for (int kt = 0; kt < 4; kt++) {
                u32 ah[4], al[4];
                ldsm4(ah, bh + kt * 32);
                ldsm4(al, bl + kt * 32);
#pragma unroll
                for (int nt = 0; nt < 2; nt++) {
                    mma_bf(acc1[mt][nt], ah, b1h[nt][kt]);
                    mma_bf(acc1[mt][nt], ah, b1l[nt][kt]);
                    mma_bf(acc1[mt][nt], al, b1h[nt][kt]);
                }
            }
        }

        // ---- epilogue1: h = relu(acc1 + P1[s] + P2[r]) -> H smem bf16 hi/lo ----
#pragma unroll
        for (int nt = 0; nt < 2; nt++) {
            const int n0 = wid * 16 + nt * 8 + cq;
            float2 p1a[4], p2a[4], p1b[4], p2b[4];
#pragma unroll
            for (int mt = 0; mt < 4; mt++) {
                const int m0 = mt * 16 + nrow, m1 = m0 + 8;
                p1a[mt] = __ldg((const float2*)(g_P + (size_t)sSS[m0] * 384 + n0));
                p2a[mt] = __ldg((const float2*)(g_P + (size_t)sSR[m0] * 384 + 128 + n0));
                p1b[mt] = __ldg((const float2*)(g_P + (size_t)sSS[m1] * 384 + n0));
                p2b[mt] = __ldg((const float2*)(g_P + (size_t)sSR[m1] * 384 + 128 + n0));
            }
#pragma unroll
            for (int mt = 0; mt < 4; mt++) {
                const int m0 = mt * 16 + nrow, m1 = m0 + 8;
                const float x0 = fmaxf(acc1[mt][nt][0] + p1a[mt].x + p2a[mt].x, 0.f);
                const float x1 = fmaxf(acc1[mt][nt][1] + p1a[mt].y + p2a[mt].y, 0.f);
                const float x2 = fmaxf(acc1[mt][nt][2] + p1b[mt].x + p2b[mt].x, 0.f);
                const float x3 = fmaxf(acc1[mt][nt][3] + p1b[mt].y + p2b[mt].y, 0.f);
                const u32 h0 = pack_bf2(x0, x1);
                const u32 h1 = pack_bf2(x2, x3);
                *(u32*)(sm + EOFF_HH + (m0 * SH_STRIDE + n0) * 2) = h0;
                *(u32*)(sm + EOFF_HH + (m1 * SH_STRIDE + n0) * 2) = h1;
                *(u32*)(sm + EOFF_HL + (m0 * SH_STRIDE + n0) * 2) =
                    pack_bf2(x0 - lowf(h0), x1 - highf(h0));
                *(u32*)(sm + EOFF_HL + (m1 * SH_STRIDE + n0) * 2) =
                    pack_bf2(x2 - lowf(h1), x3 - highf(h1));
            }
        }
        __syncthreads();

        // ---- layer 2: acc2[64,64] = h @ We2^T (+be2) ----
        float acc2[4][4];
#pragma unroll
        for (int mt = 0; mt < 4; mt++) {
            acc2[mt][0] = bb2.x; acc2[mt][1] = bb2.y;
            acc2[mt][2] = bb2.x; acc2[mt][3] = bb2.y;
        }
#pragma unroll
        for (int kt = 0; kt < 8; kt++) {
            u32 bfh[2], bfl[2];
            ldsm2(bfh, w2h + offB + kt * 32);
            ldsm2(bfl, w2l + offB + kt * 32);
#pragma unroll
            for (int mt = 0; mt < 4; mt++) {
                u32 ah[4], al[4];
                const u32 rb = mt * (16 * SH_STRIDE * 2) + kt * 32;
                ldsm4(ah, hhb + offH + rb);
                ldsm4(al, hlb + offH + rb);
                mma_bf(acc2[mt], ah, bfh);
                mma_bf(acc2[mt], ah, bfl);
                mma_bf(acc2[mt], al, bfh);
            }
        }

        // ---- epilogue2: stage fp32 (overlays AH/AL) -> float4 stores + atomics ----
        {
            const int n2 = wid * 8 + cq;
#pragma unroll
            for (int mt = 0; mt < 4; mt++) {
                const int m0 = mt * 16 + nrow, m1 = m0 + 8;
                *(float2*)(sF + m0 * 68 + n2) = make_float2(acc2[mt][0], acc2[mt][1]);
                *(float2*)(sF + m1 * 68 + n2) = make_float2(acc2[mt][2], acc2[mt][3]);
            }
        }
        __syncthreads();
        {
            const int row = tid >> 2, q = tid & 3;
            const int ge = base + row;
            if (ge < E) {
                const int ridx = sSR[row];
#pragma unroll
                for (int j = 0; j < 4; j++) {
                    const int col = (q + 4 * j) * 4;
                    const float4 v = *(const float4*)(sF + row * 68 + col);
                    *(float4*)(e_out + (size_t)ge * 64 + col) = v;
                    atomicAdd((float4*)(g_agg + (size_t)ridx * 64 + col), v);
                }
            }
        }
        par ^= 1;
    }
}

// ============================================================================
// Node kernel (proven shape): 512 threads, 128-row tiles, 1 CTA/SM.
// n = relu(agg@Wn1_a + Q[node] + bn1) @ Wn2 + bn2
__global__ __launch_bounds__(512, 1)
void node_kernel(const float* __restrict__ Wn1, const float* __restrict__ bn1,
                 const float* __restrict__ Wn2, const float* __restrict__ bn2,
                 float* __restrict__ n_out, int N)
{
    char* sm = smem_raw;
    const u32 smb = smem_u32(sm);
    const u32 ahb = smb + BOFF_AH, alb = smb + BOFF_AL;
    const u32 hhb = smb + BOFF_HH, hlb = smb + BOFF_HL;

    const int tid = threadIdx.x, wid = tid >> 5, lid = tid & 31;
    const int nrow = lid >> 2, cq = (lid & 3) * 2;
    const int mh = wid >> 3;
    const int base = blockIdx.x * 128;

    u32 b1h[4][2], b1l[4][2];
    {
        const int n = wid * 8 + nrow;
#pragma unroll
        for (int kt = 0; kt < 4; kt++)
#pragma unroll
            for (int r = 0; r < 2; r++)
                build_frag(Wn1, 128, n, kt * 16 + cq + r * 8, b1h[kt][r], b1l[kt][r]);
    }
    u32 b2h[8][2], b2l[8][2];
    {
        const int n = (wid & 7) * 8 + nrow;
#pragma unroll
        for (int kt = 0; kt < 8; kt++)
#pragma unroll
            for (int r = 0; r < 2; r++)
                build_frag(Wn2, 64, n, kt * 16 + cq + r * 8, b2h[kt][r], b2l[kt][r]);
    }
    const float2 bb1 = *(const float2*)(bn1 + wid * 8 + cq);
    const float2 bb2 = *(const float2*)(bn2 + (wid & 7) * 8 + cq);

    const int trow = (lid & 7) + ((lid >> 3) & 1) * 8;
    const int tcol = (lid >> 4) * 8;
    const u32 offA = (u32)(trow * SA_STRIDE + tcol) * 2;
    const u32 offH = (u32)(trow * SH_STRIDE + tcol) * 2;

    {
        const int row = tid >> 2, q = tid & 3;
        int g = base + row; if (g >= N) g = N - 1;
        stage_row_quarter(sm, (const float4*)(g_agg + (size_t)g * 64), row, q, BOFF_AH, BOFF_AL);
    }
    __syncthreads();

    float acc1[8][4];
#pragma unroll
    for (int mt = 0; mt < 8; mt++) {
        acc1[mt][0] = bb1.x; acc1[mt][1] = bb1.y;
        acc1[mt][2] = bb1.x; acc1[mt][3] = bb1.y;
    }
#pragma unroll
    for (int mt = 0; mt < 8; mt++) {
        const u32 bh = ahb + offA + mt * (16 * SA_STRIDE * 2);
        const u32 bl = alb + offA + mt * (16 * SA_STRIDE * 2);
#pragma unroll
        for (int kt = 0; kt < 4; kt++) {
            u32 ah[4], al[4];
            ldsm4(ah, bh + kt * 32);
            ldsm4(al, bl + kt * 32);
            mma_bf(acc1[mt], ah, b1h[kt]);
            mma_bf(acc1[mt], ah, b1l[kt]);
            mma_bf(acc1[mt], al, b1h[kt]);
        }
    }

    {
        const int n0 = wid * 8 + cq;
#pragma unroll
        for (int mt = 0; mt < 8; mt++) {
            const int m0 = mt * 16 + nrow, m1 = m0 + 8;
            int g0 = base + m0; if (g0 >= N) g0 = N - 1;
            int g1 = base + m1; if (g1 >= N) g1 = N - 1;
            const float2 qa = __ldg((const float2*)(g_P + (size_t)g0 * 384 + 256 + n0));
            const float2 qb = __ldg((const float2*)(g_P + (size_t)g1 * 384 + 256 + n0));
            const float x0 = fmaxf(acc1[mt][0] + qa.x, 0.f);
            const float x1 = fmaxf(acc1[mt][1] + qa.y, 0.f);
            const float x2 = fmaxf(acc1[mt][2] + qb.x, 0.f);
            const float x3 = fmaxf(acc1[mt][3] + qb.y, 0.f);
            const u32 h0 = pack_bf2(x0, x1);
            const u32 h1 = pack_bf2(x2, x3);
            *(u32*)(sm + BOFF_HH + (m0 * SH_STRIDE + n0) * 2) = h0;
            *(u32*)(sm + BOFF_HH + (m1 * SH_STRIDE + n0) * 2) = h1;
            *(u32*)(sm + BOFF_HL + (m0 * SH_STRIDE + n0) * 2) =
                pack_bf2(x0 - lowf(h0), x1 - highf(h0));
            *(u32*)(sm + BOFF_HL + (m1 * SH_STRIDE + n0) * 2) =
                pack_bf2(x2 - lowf(h1), x3 - highf(h1));
        }
    }
    __syncthreads();

    float acc2[4][4];
#pragma unroll
    for (int mt = 0; mt < 4; mt++) {
        acc2[mt][0] = bb2.x; acc2[mt][1] = bb2.y;
        acc2[mt][2] = bb2.x; acc2[mt][3] = bb2.y;
    }
#pragma unroll
    for (int mt = 0; mt < 4; mt++) {
        const int rowbase = (mh * 4 + mt) * 16;
        const u32 bh = hhb + offH + rowbase * (SH_STRIDE * 2);
        const u32 bl = hlb + offH + rowbase * (SH_STRIDE * 2);
#pragma unroll
        for (int kt = 0; kt < 8; kt++) {
            u32 ah[4], al[4];
            ldsm4(ah, bh + kt * 32);
            ldsm4(al, bl + kt * 32);
            mma_bf(acc2[mt], ah, b2h[kt]);
            mma_bf(acc2[mt], ah, b2l[kt]);
            mma_bf(acc2[mt], al, b2h[kt]);
        }
    }

    {
        const int n2 = (wid & 7) * 8 + cq;
#pragma unroll
        for (int mt = 0; mt < 4; mt++) {
            const int m0 = mh * 64 + mt * 16 + nrow, m1 = m0 + 8;
            const int g0 = base + m0, g1 = base + m1;
            if (g0 < N) *(float2*)(n_out + (size_t)g0 * 64 + n2) =
                            make_float2(acc2[mt][0], acc2[mt][1]);
            if (g1 < N) *(float2*)(n_out + (size_t)g1 * 64 + n2) =
                            make_float2(acc2[mt][2], acc2[mt][3]);
        }
    }
}

// ============================================================================
extern "C" void kernel_launch(void* const* d_in, const int* in_sizes, int n_in,
                              void* d_out, int out_size)
{
    const float* node_feats = (const float*)d_in[0];
    const float* edge_feats = (const float*)d_in[1];
    const float* We1 = (const float*)d_in[2];
    const float* be1 = (const float*)d_in[3];
    const float* We2 = (const float*)d_in[4];
    const float* be2 = (const float*)d_in[5];
    const float* Wn1 = (const float*)d_in[6];
    const float* bn1 = (const float*)d_in[7];
    const float* Wn2 = (const float*)d_in[8];
    const float* bn2 = (const float*)d_in[9];
    const int* senders   = (const int*)d_in[10];
    const int* receivers = (const int*)d_in[11];

    const int N = in_sizes[0] / D;
    const int E = in_sizes[1] / D;

    float* out   = (float*)d_out;
    float* e_out = out;                   // [E, D]
    float* n_out = out + (size_t)E * D;   // [N, D]

    cudaFuncSetAttribute(pproj_kernel, cudaFuncAttributeMaxDynamicSharedMemorySize, PPROJ_SMEM);
    cudaFuncSetAttribute(edge_kernel,  cudaFuncAttributeMaxDynamicSharedMemorySize, EDGE_SMEM);
    cudaFuncSetAttribute(node_kernel,  cudaFuncAttributeMaxDynamicSharedMemorySize, BIG_SMEM);

    int dev = 0, sms = 148;
    cudaGetDevice(&dev);
    cudaDeviceGetAttribute(&sms, cudaDevAttrMultiProcessorCount, dev);

    pproj_kernel<<<(N + 127) / 128, 512, PPROJ_SMEM>>>(node_feats, We1, Wn1, N);

    edge_kernel<<<2 * sms, 256, EDGE_SMEM>>>(edge_feats, We1, be1, We2, be2,
                                             senders, receivers, e_out, E);

    node_kernel<<<(N + 127) / 128, 512, BIG_SMEM>>>(Wn1, bn1, Wn2, bn2, n_out, N);
}

// round 13
// speedup vs baseline: 1.1540x; 1.1540x over previous
#include <cuda_runtime.h>
#include <cuda_bf16.h>

// Problem constants (fixed dataset: N=50000, E=800000, D=64, H=128)
#define D  64
#define H  128
#define MAXN 50000

#define SA_STRIDE 72     // bf16 elems per row (64 + 8 pad)
#define SH_STRIDE 136    // bf16 elems per row (128 + 8 pad)

// Scratch
__device__ float g_agg[MAXN * D];      // segment_sum target
__device__ float g_P[MAXN * 384];      // [0:128]=nf@We1_s, [128:256]=nf@We1_r, [256:384]=nf@Wn1_n

typedef unsigned int u32;
typedef unsigned long long u64;

extern __shared__ char smem_raw[];

// ---- edge kernel smem map (64-row tiles, 256 threads, 2 CTAs/SM) ----
#define EOFF_AH   512
#define EOFF_AL   9728
#define EOFF_HH   18944
#define EOFF_HL   36352
#define EOFF_W2H  53760
#define EOFF_W2L  71168
#define EDGE_SMEM 88576

// ---- node/pproj smem map (128-row tiles, 512 threads, 1 CTA/SM) ----
#define BOFF_AH   1024
#define BOFF_AL   19456
#define BOFF_HH   37888
#define BOFF_HL   72704
#define BIG_SMEM  107520
#define PPROJ_SMEM 37888

// ============================================================================
__device__ __forceinline__ u32 smem_u32(const void* p) {
    u32 a; asm("{ .reg .u64 t; cvta.to.shared.u64 t, %1; cvt.u32.u64 %0, t; }" : "=r"(a) : "l"(p));
    return a;
}
__device__ __forceinline__ u32 pack_bf2(float lo, float hi) {
    u32 r; asm("cvt.rn.bf16x2.f32 %0, %1, %2;" : "=r"(r) : "f"(hi), "f"(lo)); return r;
}
__device__ __forceinline__ float lowf(u32 p)  { return __uint_as_float(p << 16); }
__device__ __forceinline__ float highf(u32 p) { return __uint_as_float(p & 0xFFFF0000u); }

__device__ __forceinline__ void ldsm4(u32* r, u32 addr) {
    asm volatile("ldmatrix.sync.aligned.m8n8.x4.shared.b16 {%0,%1,%2,%3}, [%4];"
        : "=r"(r[0]), "=r"(r[1]), "=r"(r[2]), "=r"(r[3]) : "r"(addr));
}
__device__ __forceinline__ void ldsm2(u32* r, u32 addr) {
    asm volatile("ldmatrix.sync.aligned.m8n8.x2.shared.b16 {%0,%1}, [%2];"
        : "=r"(r[0]), "=r"(r[1]) : "r"(addr));
}
__device__ __forceinline__ void mma_bf(float* c, const u32* a, const u32* b) {
    asm volatile("mma.sync.aligned.m16n8k16.row.col.f32.bf16.bf16.f32 "
        "{%0,%1,%2,%3}, {%4,%5,%6,%7}, {%8,%9}, {%0,%1,%2,%3};"
        : "+f"(c[0]), "+f"(c[1]), "+f"(c[2]), "+f"(c[3])
        : "r"(a[0]), "r"(a[1]), "r"(a[2]), "r"(a[3]), "r"(b[0]), "r"(b[1]));
}
__device__ __forceinline__ void build_frag(const float* __restrict__ W, int ldw,
                                           int n, int k0, u32& hi, u32& lo) {
    const float w0 = W[k0 * ldw + n];
    const float w1 = W[(k0 + 1) * ldw + n];
    hi = pack_bf2(w0, w1);
    lo = pack_bf2(w0 - lowf(hi), w1 - highf(hi));
}
__device__ __forceinline__ void stage_row_quarter(char* sm, const float4* src4,
                                                  int row, int q, int offH, int offL) {
#pragma unroll
    for (int j = 0; j < 4; j++) {
        const float4 v = src4[q + 4 * j];
        const int col = (q + 4 * j) * 4;
        const u32 off = (u32)(row * SA_STRIDE + col) * 2;
        const u32 h0 = pack_bf2(v.x, v.y);
        const u32 h1 = pack_bf2(v.z, v.w);
        *(u32*)(sm + offH + off)     = h0;
        *(u32*)(sm + offH + off + 4) = h1;
        *(u32*)(sm + offL + off)     = pack_bf2(v.x - lowf(h0), v.y - highf(h0));
        *(u32*)(sm + offL + off + 4) = pack_bf2(v.z - lowf(h1), v.w - highf(h1));
    }
}
__device__ __forceinline__ void stage_w2t(char* sm, const float* __restrict__ W2, int tid) {
    for (int i = tid; i < 64 * 64; i += 256) {
        const int n = i >> 6, kp = i & 63;
        const float w0 = W2[(2 * kp) * 64 + n];
        const float w1 = W2[(2 * kp + 1) * 64 + n];
        const u32 hi = pack_bf2(w0, w1);
        const u32 lo = pack_bf2(w0 - lowf(hi), w1 - highf(hi));
        const u32 off = (u32)(n * SH_STRIDE + 2 * kp) * 2;
        *(u32*)(sm + EOFF_W2H + off) = hi;
        *(u32*)(sm + EOFF_W2L + off) = lo;
    }
}

// ============================================================================
__global__ void zero_agg_kernel(int n4) {
    int i = blockIdx.x * blockDim.x + threadIdx.x;
    if (i < n4) reinterpret_cast<float4*>(g_agg)[i] = make_float4(0.f, 0.f, 0.f, 0.f);
}

// ============================================================================
// P projection (mma bf16 3-term): g_P[n][seg*128+c] for seg in {We1_s, We1_r, Wn1_n}
__global__ __launch_bounds__(512)
void pproj_kernel(const float* __restrict__ nodef,
                  const float* __restrict__ We1, const float* __restrict__ Wn1, int N)
{
    char* sm = smem_raw;
    const u32 smb = smem_u32(sm);
    const u32 ahb = smb + BOFF_AH, alb = smb + BOFF_AL;

    const int tid = threadIdx.x, wid = tid >> 5, lid = tid & 31;
    const int nrow = lid >> 2, cq = (lid & 3) * 2;
    const int base = blockIdx.x * 128;

    u32 bh[3][4][2], bl[3][4][2];
    {
        const int n = wid * 8 + nrow;
#pragma unroll
        for (int kt = 0; kt < 4; kt++)
#pragma unroll
            for (int r = 0; r < 2; r++) {
                const int k = kt * 16 + cq + r * 8;
                build_frag(We1 + (size_t)64 * 128, 128, n, k, bh[0][kt][r], bl[0][kt][r]);
                build_frag(We1 + (size_t)128 * 128, 128, n, k, bh[1][kt][r], bl[1][kt][r]);
                build_frag(Wn1 + (size_t)64 * 128, 128, n, k, bh[2][kt][r], bl[2][kt][r]);
            }
    }
    {
        const int row = tid >> 2, q = tid & 3;
        int g = base + row; if (g >= N) g = N - 1;
        stage_row_quarter(sm, (const float4*)(nodef + (size_t)g * 64), row, q, BOFF_AH, BOFF_AL);
    }
    __syncthreads();

    const int trow = (lid & 7) + ((lid >> 3) & 1) * 8;
    const int tcol = (lid >> 4) * 8;
    const u32 offA = (u32)(trow * SA_STRIDE + tcol) * 2;
    const int n0 = wid * 8 + cq;

#pragma unroll
    for (int mt = 0; mt < 8; mt++) {
        u32 ah[4][4], al[4][4];
        const u32 bhA = ahb + offA + mt * (16 * SA_STRIDE * 2);
        const u32 blA = alb + offA + mt * (16 * SA_STRIDE * 2);
#pragma unroll
        for (int kt = 0; kt < 4; kt++) {
            ldsm4(ah[kt], bhA + kt * 32);
            ldsm4(al[kt], blA + kt * 32);
        }
        const int g0 = base + mt * 16 + nrow, g1 = g0 + 8;
#pragma unroll
        for (int seg = 0; seg < 3; seg++) {
            float acc[4] = {0.f, 0.f, 0.f, 0.f};
#pragma unroll
            for (int kt = 0; kt < 4; kt++) {
                mma_bf(acc, ah[kt], bh[seg][kt]);
                mma_bf(acc, ah[kt], bl[seg][kt]);
                mma_bf(acc, al[kt], bh[seg][kt]);
            }
            if (g0 < N) *(float2*)(g_P + (size_t)g0 * 384 + seg * 128 + n0) =
                            make_float2(acc[0], acc[1]);
            if (g1 < N) *(float2*)(g_P + (size_t)g1 * 384 + seg * 128 + n0) =
                            make_float2(acc[2], acc[3]);
        }
    }
}

// ============================================================================
// Edge kernel (round-8 proven form): persistent, 256 threads, 2 CTAs/SM,
// 64-edge tiles, epilogue-__ldg P gather.
__global__ __launch_bounds__(256, 2)
void edge_kernel(const float* __restrict__ edgef,
                 const float* __restrict__ We1, const float* __restrict__ be1,
                 const float* __restrict__ We2, const float* __restrict__ be2,
                 const int* __restrict__ senders, const int* __restrict__ recvs,
                 float* __restrict__ e_out, int E)
{
    char* sm = smem_raw;
    int* sSS = (int*)sm;
    int* sSR = (int*)(sm + 256);
    float* sF = (float*)(sm + EOFF_AH);       // epilogue2 fp32 staging [64][68]
    const u32 smb = smem_u32(sm);
    const u32 ahb = smb + EOFF_AH, alb = smb + EOFF_AL;
    const u32 hhb = smb + EOFF_HH, hlb = smb + EOFF_HL;
    const u32 w2h = smb + EOFF_W2H, w2l = smb + EOFF_W2L;

    const int tid = threadIdx.x, wid = tid >> 5, lid = tid & 31;
    const int nrow = lid >> 2, cq = (lid & 3) * 2;

    stage_w2t(sm, We2, tid);

    u32 b1h[2][4][2], b1l[2][4][2];
#pragma unroll
    for (int nt = 0; nt < 2; nt++) {
        const int n = wid * 16 + nt * 8 + nrow;
#pragma unroll
        for (int kt = 0; kt < 4; kt++)
#pragma unroll
            for (int r = 0; r < 2; r++)
                build_frag(We1, 128, n, kt * 16 + cq + r * 8, b1h[nt][kt][r], b1l[nt][kt][r]);
    }
    float2 bb1[2];
    bb1[0] = *(const float2*)(be1 + wid * 16 + cq);
    bb1[1] = *(const float2*)(be1 + wid * 16 + 8 + cq);
    const float2 bb2 = *(const float2*)(be2 + wid * 8 + cq);

    const int trow = (lid & 7) + ((lid >> 3) & 1) * 8;
    const int tcol = (lid >> 4) * 8;
    const u32 offA = (u32)(trow * SA_STRIDE + tcol) * 2;
    const u32 offH = (u32)(trow * SH_STRIDE + tcol) * 2;
    const u32 offB = (u32)((wid * 8 + (lid & 7)) * SH_STRIDE + ((lid >> 3) & 1) * 8) * 2;

    const int nTiles = (E + 63) / 64;

    for (int tile = blockIdx.x; tile < nTiles; tile += gridDim.x) {
        const int base = tile * 64;
        __syncthreads();

        // ---- stage indices + A ----
        if (tid < 64) {
            int g = base + tid; if (g >= E) g = E - 1;
            sSS[tid] = senders[g];
            sSR[tid] = recvs[g];
        }
        {
            const int row = tid >> 2, q = tid & 3;
            int ge = base + row; if (ge >= E) ge = E - 1;
            stage_row_quarter(sm, (const float4*)(edgef + (size_t)ge * 64), row, q, EOFF_AH, EOFF_AL);
        }
        __syncthreads();

        // ---- layer 1: acc1[64,128] = A @ We1_e^T (+be1) ----
        float acc1[4][2][4];
#pragma unroll
        for (int mt = 0; mt < 4; mt++)
#pragma unroll
            for (int nt = 0; nt < 2; nt++) {
                acc1[mt][nt][0] = bb1[nt].x; acc1[mt][nt][1] = bb1[nt].y;
                acc1[mt][nt][2] = bb1[nt].x; acc1[mt][nt][3] = bb1[nt].y;
            }
#pragma unroll
        for (int mt = 0; mt < 4; mt++) {
            const u32 bh = ahb + offA + mt * (16 * SA_STRIDE * 2);
            const u32 bl = alb + offA + mt * (16 * SA_STRIDE * 2);
#pragma unroll
            for (int kt = 0; kt < 4; kt++) {
                u32 ah[4], al[4];
                ldsm4(ah, bh + kt * 32);
                ldsm4(al, bl + kt * 32);
#pragma unroll
                for (int nt = 0; nt < 2; nt++) {
                    mma_bf(acc1[mt][nt], ah, b1h[nt][kt]);
                    mma_bf(acc1[mt][nt], ah, b1l[nt][kt]);
                    mma_bf(acc1[mt][nt], al, b1h[nt][kt]);
                }
            }
        }

        // ---- epilogue1: h = relu(acc1 + P1[s] + P2[r]) -> H smem bf16 hi/lo ----
#pragma unroll
        for (int nt = 0; nt < 2; nt++) {
            const int n0 = wid * 16 + nt * 8 + cq;
            float2 p1a[4], p2a[4], p1b[4], p2b[4];
#pragma unroll
            for (int mt = 0; mt < 4; mt++) {
                const int m0 = mt * 16 + nrow, m1 = m0 + 8;
                p1a[mt] = __ldg((const float2*)(g_P + (size_t)sSS[m0] * 384 + n0));
                p2a[mt] = __ldg((const float2*)(g_P + (size_t)sSR[m0] * 384 + 128 + n0));
                p1b[mt] = __ldg((const float2*)(g_P + (size_t)sSS[m1] * 384 + n0));
                p2b[mt] = __ldg((const float2*)(g_P + (size_t)sSR[m1] * 384 + 128 + n0));
            }
#pragma unroll
            for (int mt = 0; mt < 4; mt++) {
                const int m0 = mt * 16 + nrow, m1 = m0 + 8;
                const float x0 = fmaxf(acc1[mt][nt][0] + p1a[mt].x + p2a[mt].x, 0.f);
                const float x1 = fmaxf(acc1[mt][nt][1] + p1a[mt].y + p2a[mt].y, 0.f);
                const float x2 = fmaxf(acc1[mt][nt][2] + p1b[mt].x + p2b[mt].x, 0.f);
                const float x3 = fmaxf(acc1[mt][nt][3] + p1b[mt].y + p2b[mt].y, 0.f);
                const u32 h0 = pack_bf2(x0, x1);
                const u32 h1 = pack_bf2(x2, x3);
                *(u32*)(sm + EOFF_HH + (m0 * SH_STRIDE + n0) * 2) = h0;
                *(u32*)(sm + EOFF_HH + (m1 * SH_STRIDE + n0) * 2) = h1;
                *(u32*)(sm + EOFF_HL + (m0 * SH_STRIDE + n0) * 2) =
                    pack_bf2(x0 - lowf(h0), x1 - highf(h0));
                *(u32*)(sm + EOFF_HL + (m1 * SH_STRIDE + n0) * 2) =
                    pack_bf2(x2 - lowf(h1), x3 - highf(h1));
            }
        }
        __syncthreads();

        // ---- layer 2: acc2[64,64] = h @ We2^T (+be2); B frags via ldmatrix ----
        float acc2[4][4];
#pragma unroll
        for (int mt = 0; mt < 4; mt++) {
            acc2[mt][0] = bb2.x; acc2[mt][1] = bb2.y;
            acc2[mt][2] = bb2.x; acc2[mt][3] = bb2.y;
        }
#pragma unroll
        for (int kt = 0; kt < 8; kt++) {
            u32 bfh[2], bfl[2];
            ldsm2(bfh, w2h + offB + kt * 32);
            ldsm2(bfl, w2l + offB + kt * 32);
#pragma unroll
            for (int mt = 0; mt < 4; mt++) {
                u32 ah[4], al[4];
                const u32 rb = mt * (16 * SH_STRIDE * 2) + kt * 32;
                ldsm4(ah, hhb + offH + rb);
                ldsm4(al, hlb + offH + rb);
                mma_bf(acc2[mt], ah, bfh);
                mma_bf(acc2[mt], ah, bfl);
                mma_bf(acc2[mt], al, bfh);
            }
        }

        // ---- epilogue2: stage fp32 -> float4 stores + atomics ----
        {
            const int n2 = wid * 8 + cq;
#pragma unroll
            for (int mt = 0; mt < 4; mt++) {
                const int m0 = mt * 16 + nrow, m1 = m0 + 8;
                *(float2*)(sF + m0 * 68 + n2) = make_float2(acc2[mt][0], acc2[mt][1]);
                *(float2*)(sF + m1 * 68 + n2) = make_float2(acc2[mt][2], acc2[mt][3]);
            }
        }
        __syncthreads();
        {
            const int row = tid >> 2, q = tid & 3;
            const int ge = base + row;
            if (ge < E) {
                const int ridx = sSR[row];
#pragma unroll
                for (int j = 0; j < 4; j++) {
                    const int col = (q + 4 * j) * 4;
                    const float4 v = *(const float4*)(sF + row * 68 + col);
                    *(float4*)(e_out + (size_t)ge * 64 + col) = v;
                    atomicAdd((float4*)(g_agg + (size_t)ridx * 64 + col), v);
                }
            }
        }
    }
}

// ============================================================================
// Node kernel (proven shape): 512 threads, 128-row tiles, 1 CTA/SM.
// n = relu(agg@Wn1_a + Q[node] + bn1) @ Wn2 + bn2
__global__ __launch_bounds__(512, 1)
void node_kernel(const float* __restrict__ Wn1, const float* __restrict__ bn1,
                 const float* __restrict__ Wn2, const float* __restrict__ bn2,
                 float* __restrict__ n_out, int N)
{
    char* sm = smem_raw;
    const u32 smb = smem_u32(sm);
    const u32 ahb = smb + BOFF_AH, alb = smb + BOFF_AL;
    const u32 hhb = smb + BOFF_HH, hlb = smb + BOFF_HL;

    const int tid = threadIdx.x, wid = tid >> 5, lid = tid & 31;
    const int nrow = lid >> 2, cq = (lid & 3) * 2;
    const int mh = wid >> 3;
    const int base = blockIdx.x * 128;

    u32 b1h[4][2], b1l[4][2];
    {
        const int n = wid * 8 + nrow;
#pragma unroll
        for (int kt = 0; kt < 4; kt++)
#pragma unroll
            for (int r = 0; r < 2; r++)
                build_frag(Wn1, 128, n, kt * 16 + cq + r * 8, b1h[kt][r], b1l[kt][r]);
    }
    u32 b2h[8][2], b2l[8][2];
    {
        const int n = (wid & 7) * 8 + nrow;
#pragma unroll
        for (int kt = 0; kt < 8; kt++)
#pragma unroll
            for (int r = 0; r < 2; r++)
                build_frag(Wn2, 64, n, kt * 16 + cq + r * 8, b2h[kt][r], b2l[kt][r]);
    }
    const float2 bb1 = *(const float2*)(bn1 + wid * 8 + cq);
    const float2 bb2 = *(const float2*)(bn2 + (wid & 7) * 8 + cq);

    const int trow = (lid & 7) + ((lid >> 3) & 1) * 8;
    const int tcol = (lid >> 4) * 8;
    const u32 offA = (u32)(trow * SA_STRIDE + tcol) * 2;
    const u32 offH = (u32)(trow * SH_STRIDE + tcol) * 2;

    {
        const int row = tid >> 2, q = tid & 3;
        int g = base + row; if (g >= N) g = N - 1;
        stage_row_quarter(sm, (const float4*)(g_agg + (size_t)g * 64), row, q, BOFF_AH, BOFF_AL);
    }
    __syncthreads();

    float acc1[8][4];
#pragma unroll
    for (int mt = 0; mt < 8; mt++) {
        acc1[mt][0] = bb1.x; acc1[mt][1] = bb1.y;
        acc1[mt][2] = bb1.x; acc1[mt][3] = bb1.y;
    }
#pragma unroll
    for (int mt = 0; mt < 8; mt++) {
        const u32 bh = ahb + offA + mt * (16 * SA_STRIDE * 2);
        const u32 bl = alb + offA + mt * (16 * SA_STRIDE * 2);
#pragma unroll
        for (int kt = 0; kt < 4; kt++) {
            u32 ah[4], al[4];
            ldsm4(ah, bh + kt * 32);
            ldsm4(al, bl + kt * 32);
            mma_bf(acc1[mt], ah, b1h[kt]);
            mma_bf(acc1[mt], ah, b1l[kt]);
            mma_bf(acc1[mt], al, b1h[kt]);
        }
    }

    {
        const int n0 = wid * 8 + cq;
#pragma unroll
        for (int mt = 0; mt < 8; mt++) {
            const int m0 = mt * 16 + nrow, m1 = m0 + 8;
            int g0 = base + m0; if (g0 >= N) g0 = N - 1;
            int g1 = base + m1; if (g1 >= N) g1 = N - 1;
            const float2 qa = __ldg((const float2*)(g_P + (size_t)g0 * 384 + 256 + n0));
            const float2 qb = __ldg((const float2*)(g_P + (size_t)g1 * 384 + 256 + n0));
            const float x0 = fmaxf(acc1[mt][0] + qa.x, 0.f);
            const float x1 = fmaxf(acc1[mt][1] + qa.y, 0.f);
            const float x2 = fmaxf(acc1[mt][2] + qb.x, 0.f);
            const float x3 = fmaxf(acc1[mt][3] + qb.y, 0.f);
            const u32 h0 = pack_bf2(x0, x1);
            const u32 h1 = pack_bf2(x2, x3);
            *(u32*)(sm + BOFF_HH + (m0 * SH_STRIDE + n0) * 2) = h0;
            *(u32*)(sm + BOFF_HH + (m1 * SH_STRIDE + n0) * 2) = h1;
            *(u32*)(sm + BOFF_HL + (m0 * SH_STRIDE + n0) * 2) =
                pack_bf2(x0 - lowf(h0), x1 - highf(h0));
            *(u32*)(sm + BOFF_HL + (m1 * SH_STRIDE + n0) * 2) =
                pack_bf2(x2 - lowf(h1), x3 - highf(h1));
        }
    }
    __syncthreads();

    float acc2[4][4];
#pragma unroll
    for (int mt = 0; mt < 4; mt++) {
        acc2[mt][0] = bb2.x; acc2[mt][1] = bb2.y;
        acc2[mt][2] = bb2.x; acc2[mt][3] = bb2.y;
    }
#pragma unroll
    for (int mt = 0; mt < 4; mt++) {
        const int rowbase = (mh * 4 + mt) * 16;
        const u32 bh = hhb + offH + rowbase * (SH_STRIDE * 2);
        const u32 bl = hlb + offH + rowbase * (SH_STRIDE * 2);
#pragma unroll
        for (int kt = 0; kt < 8; kt++) {
            u32 ah[4], al[4];
            ldsm4(ah, bh + kt * 32);
            ldsm4(al, bl + kt * 32);
            mma_bf(acc2[mt], ah, b2h[kt]);
            mma_bf(acc2[mt], ah, b2l[kt]);
            mma_bf(acc2[mt], al, b2h[kt]);
        }
    }

    {
        const int n2 = (wid & 7) * 8 + cq;
#pragma unroll
        for (int mt = 0; mt < 4; mt++) {
            const int m0 = mh * 64 + mt * 16 + nrow, m1 = m0 + 8;
            const int g0 = base + m0, g1 = base + m1;
            if (g0 < N) *(float2*)(n_out + (size_t)g0 * 64 + n2) =
                            make_float2(acc2[mt][0], acc2[mt][1]);
            if (g1 < N) *(float2*)(n_out + (size_t)g1 * 64 + n2) =
                            make_float2(acc2[mt][2], acc2[mt][3]);
        }
    }
}

// ============================================================================
extern "C" void kernel_launch(void* const* d_in, const int* in_sizes, int n_in,
                              void* d_out, int out_size)
{
    const float* node_feats = (const float*)d_in[0];
    const float* edge_feats = (const float*)d_in[1];
    const float* We1 = (const float*)d_in[2];
    const float* be1 = (const float*)d_in[3];
    const float* We2 = (const float*)d_in[4];
    const float* be2 = (const float*)d_in[5];
    const float* Wn1 = (const float*)d_in[6];
    const float* bn1 = (const float*)d_in[7];
    const float* Wn2 = (const float*)d_in[8];
    const float* bn2 = (const float*)d_in[9];
    const int* senders   = (const int*)d_in[10];
    const int* receivers = (const int*)d_in[11];

    const int N = in_sizes[0] / D;
    const int E = in_sizes[1] / D;

    float* out   = (float*)d_out;
    float* e_out = out;                   // [E, D]
    float* n_out = out + (size_t)E * D;   // [N, D]

    cudaFuncSetAttribute(pproj_kernel, cudaFuncAttributeMaxDynamicSharedMemorySize, PPROJ_SMEM);
    cudaFuncSetAttribute(edge_kernel,  cudaFuncAttributeMaxDynamicSharedMemorySize, EDGE_SMEM);
    cudaFuncSetAttribute(node_kernel,  cudaFuncAttributeMaxDynamicSharedMemorySize, BIG_SMEM);

    int dev = 0, sms = 148;
    cudaGetDevice(&dev);
    cudaDeviceGetAttribute(&sms, cudaDevAttrMultiProcessorCount, dev);

    const int n4 = N * D / 4;
    zero_agg_kernel<<<(n4 + 255) / 256, 256>>>(n4);

    pproj_kernel<<<(N + 127) / 128, 512, PPROJ_SMEM>>>(node_feats, We1, Wn1, N);

    edge_kernel<<<2 * sms, 256, EDGE_SMEM>>>(edge_feats, We1, be1, We2, be2,
                                             senders, receivers, e_out, E);

    node_kernel<<<(N + 127) / 128, 512, BIG_SMEM>>>(Wn1, bn1, Wn2, bn2, n_out, N);
}

// round 14
// speedup vs baseline: 1.1598x; 1.0051x over previous
#include <cuda_runtime.h>
#include <cuda_bf16.h>

// Problem constants (fixed dataset: N=50000, E=800000, D=64, H=128)
#define D  64
#define H  128
#define MAXN 50000

#define SA_STRIDE 72     // bf16 elems per row (64 + 8 pad)
#define SH_STRIDE 136    // bf16 elems per row (128 + 8 pad)

// Scratch
__device__ float g_agg[MAXN * D];      // segment_sum target
__device__ float g_P[MAXN * 384];      // [0:128]=nf@We1_s, [128:256]=nf@We1_r, [256:384]=nf@Wn1_n

typedef unsigned int u32;
typedef unsigned long long u64;

extern __shared__ char smem_raw[];

// ---- edge kernel smem map (64-row tiles, 256 threads, 2 CTAs/SM) ----
#define EOFF_AH   512
#define EOFF_AL   9728
#define EOFF_HH   18944
#define EOFF_HL   36352
#define EOFF_W2H  53760
#define EOFF_W2L  71168
#define EDGE_SMEM 88576

// ---- node/pproj smem map (128-row tiles, 512 threads, 1 CTA/SM) ----
#define BOFF_AH   1024
#define BOFF_AL   19456
#define BOFF_HH   37888
#define BOFF_HL   72704
#define BIG_SMEM  107520
#define PPROJ_SMEM 37888

// ============================================================================
__device__ __forceinline__ u32 smem_u32(const void* p) {
    u32 a; asm("{ .reg .u64 t; cvta.to.shared.u64 t, %1; cvt.u32.u64 %0, t; }" : "=r"(a) : "l"(p));
    return a;
}
__device__ __forceinline__ u32 pack_bf2(float lo, float hi) {
    u32 r; asm("cvt.rn.bf16x2.f32 %0, %1, %2;" : "=r"(r) : "f"(hi), "f"(lo)); return r;
}
__device__ __forceinline__ float lowf(u32 p)  { return __uint_as_float(p << 16); }
__device__ __forceinline__ float highf(u32 p) { return __uint_as_float(p & 0xFFFF0000u); }

__device__ __forceinline__ void ldsm4(u32* r, u32 addr) {
    asm volatile("ldmatrix.sync.aligned.m8n8.x4.shared.b16 {%0,%1,%2,%3}, [%4];"
        : "=r"(r[0]), "=r"(r[1]), "=r"(r[2]), "=r"(r[3]) : "r"(addr));
}
__device__ __forceinline__ void ldsm2(u32* r, u32 addr) {
    asm volatile("ldmatrix.sync.aligned.m8n8.x2.shared.b16 {%0,%1}, [%2];"
        : "=r"(r[0]), "=r"(r[1]) : "r"(addr));
}
__device__ __forceinline__ void mma_bf(float* c, const u32* a, const u32* b) {
    asm volatile("mma.sync.aligned.m16n8k16.row.col.f32.bf16.bf16.f32 "
        "{%0,%1,%2,%3}, {%4,%5,%6,%7}, {%8,%9}, {%0,%1,%2,%3};"
        : "+f"(c[0]), "+f"(c[1]), "+f"(c[2]), "+f"(c[3])
        : "r"(a[0]), "r"(a[1]), "r"(a[2]), "r"(a[3]), "r"(b[0]), "r"(b[1]));
}
__device__ __forceinline__ void build_frag(const float* __restrict__ W, int ldw,
                                           int n, int k0, u32& hi, u32& lo) {
    const float w0 = W[k0 * ldw + n];
    const float w1 = W[(k0 + 1) * ldw + n];
    hi = pack_bf2(w0, w1);
    lo = pack_bf2(w0 - lowf(hi), w1 - highf(hi));
}
__device__ __forceinline__ void stage_row_quarter(char* sm, const float4* src4,
                                                  int row, int q, int offH, int offL) {
#pragma unroll
    for (int j = 0; j < 4; j++) {
        const float4 v = src4[q + 4 * j];
        const int col = (q + 4 * j) * 4;
        const u32 off = (u32)(row * SA_STRIDE + col) * 2;
        const u32 h0 = pack_bf2(v.x, v.y);
        const u32 h1 = pack_bf2(v.z, v.w);
        *(u32*)(sm + offH + off)     = h0;
        *(u32*)(sm + offH + off + 4) = h1;
        *(u32*)(sm + offL + off)     = pack_bf2(v.x - lowf(h0), v.y - highf(h0));
        *(u32*)(sm + offL + off + 4) = pack_bf2(v.z - lowf(h1), v.w - highf(h1));
    }
}
__device__ __forceinline__ void stage_w2t(char* sm, const float* __restrict__ W2, int tid) {
    for (int i = tid; i < 64 * 64; i += 256) {
        const int n = i >> 6, kp = i & 63;
        const float w0 = W2[(2 * kp) * 64 + n];
        const float w1 = W2[(2 * kp + 1) * 64 + n];
        const u32 hi = pack_bf2(w0, w1);
        const u32 lo = pack_bf2(w0 - lowf(hi), w1 - highf(hi));
        const u32 off = (u32)(n * SH_STRIDE + 2 * kp) * 2;
        *(u32*)(sm + EOFF_W2H + off) = hi;
        *(u32*)(sm + EOFF_W2L + off) = lo;
    }
}

// ============================================================================
// Combined prep kernel: blocks [0, nodeTiles) do the P projection;
// blocks [nodeTiles, nodeTiles + ZB) zero g_agg (independent work, one launch).
#define ZB 96
__global__ __launch_bounds__(512)
void prep_kernel(const float* __restrict__ nodef,
                 const float* __restrict__ We1, const float* __restrict__ Wn1,
                 int N, int nodeTiles)
{
    if (blockIdx.x >= (unsigned)nodeTiles) {
        // zero g_agg: grid-stride over N*16 float4s
        const int zb = blockIdx.x - nodeTiles;
        float4* dst = (float4*)g_agg;
        const int n4 = N * 16;
        for (int i = zb * 512 + threadIdx.x; i < n4; i += ZB * 512)
            dst[i] = make_float4(0.f, 0.f, 0.f, 0.f);
        return;
    }

    char* sm = smem_raw;
    const u32 smb = smem_u32(sm);
    const u32 ahb = smb + BOFF_AH, alb = smb + BOFF_AL;

    const int tid = threadIdx.x, wid = tid >> 5, lid = tid & 31;
    const int nrow = lid >> 2, cq = (lid & 3) * 2;
    const int base = blockIdx.x * 128;

    u32 bh[3][4][2], bl[3][4][2];
    {
        const int n = wid * 8 + nrow;
#pragma unroll
        for (int kt = 0; kt < 4; kt++)
#pragma unroll
            for (int r = 0; r < 2; r++) {
                const int k = kt * 16 + cq + r * 8;
                build_frag(We1 + (size_t)64 * 128, 128, n, k, bh[0][kt][r], bl[0][kt][r]);
                build_frag(We1 + (size_t)128 * 128, 128, n, k, bh[1][kt][r], bl[1][kt][r]);
                build_frag(Wn1 + (size_t)64 * 128, 128, n, k, bh[2][kt][r], bl[2][kt][r]);
            }
    }
    {
        const int row = tid >> 2, q = tid & 3;
        int g = base + row; if (g >= N) g = N - 1;
        stage_row_quarter(sm, (const float4*)(nodef + (size_t)g * 64), row, q, BOFF_AH, BOFF_AL);
    }
    __syncthreads();

    const int trow = (lid & 7) + ((lid >> 3) & 1) * 8;
    const int tcol = (lid >> 4) * 8;
    const u32 offA = (u32)(trow * SA_STRIDE + tcol) * 2;
    const int n0 = wid * 8 + cq;

#pragma unroll
    for (int mt = 0; mt < 8; mt++) {
        u32 ah[4][4], al[4][4];
        const u32 bhA = ahb + offA + mt * (16 * SA_STRIDE * 2);
        const u32 blA = alb + offA + mt * (16 * SA_STRIDE * 2);
#pragma unroll
        for (int kt = 0; kt < 4; kt++) {
            ldsm4(ah[kt], bhA + kt * 32);
            ldsm4(al[kt], blA + kt * 32);
        }
        const int g0 = base + mt * 16 + nrow, g1 = g0 + 8;
#pragma unroll
        for (int seg = 0; seg < 3; seg++) {
            float acc[4] = {0.f, 0.f, 0.f, 0.f};
#pragma unroll
            for (int kt = 0; kt < 4; kt++) {
                mma_bf(acc, ah[kt], bh[seg][kt]);
                mma_bf(acc, ah[kt], bl[seg][kt]);
                mma_bf(acc, al[kt], bh[seg][kt]);
            }
            if (g0 < N) *(float2*)(g_P + (size_t)g0 * 384 + seg * 128 + n0) =
                            make_float2(acc[0], acc[1]);
            if (g1 < N) *(float2*)(g_P + (size_t)g1 * 384 + seg * 128 + n0) =
                            make_float2(acc[2], acc[3]);
        }
    }
}

// ============================================================================
// Edge kernel: persistent, 256 threads, 2 CTAs/SM, 64-edge tiles.
// MMA loops restructured: consecutive mmas hit DISTINCT accumulators
// (same-acc reuse gap 4-8) to break HMMA latency chains. Per-accumulator
// accumulation ORDER is unchanged -> bit-identical results.
__global__ __launch_bounds__(256, 2)
void edge_kernel(const float* __restrict__ edgef,
                 const float* __restrict__ We1, const float* __restrict__ be1,
                 const float* __restrict__ We2, const float* __restrict__ be2,
                 const int* __restrict__ senders, const int* __restrict__ recvs,
                 float* __restrict__ e_out, int E)
{
    char* sm = smem_raw;
    int* sSS = (int*)sm;
    int* sSR = (int*)(sm + 256);
    float* sF = (float*)(sm + EOFF_AH);       // epilogue2 fp32 staging [64][68]
    const u32 smb = smem_u32(sm);
    const u32 ahb = smb + EOFF_AH, alb = smb + EOFF_AL;
    const u32 hhb = smb + EOFF_HH, hlb = smb + EOFF_HL;
    const u32 w2h = smb + EOFF_W2H, w2l = smb + EOFF_W2L;

    const int tid = threadIdx.x, wid = tid >> 5, lid = tid & 31;
    const int nrow = lid >> 2, cq = (lid & 3) * 2;

    stage_w2t(sm, We2, tid);

    u32 b1h[2][4][2], b1l[2][4][2];
#pragma unroll
    for (int nt = 0; nt < 2; nt++) {
        const int n = wid * 16 + nt * 8 + nrow;
#pragma unroll
        for (int kt = 0; kt < 4; kt++)
#pragma unroll
            for (int r = 0; r < 2; r++)
                build_frag(We1, 128, n, kt * 16 + cq + r * 8, b1h[nt][kt][r], b1l[nt][kt][r]);
    }
    float2 bb1[2];
    bb1[0] = *(const float2*)(be1 + wid * 16 + cq);
    bb1[1] = *(const float2*)(be1 + wid * 16 + 8 + cq);
    const float2 bb2 = *(const float2*)(be2 + wid * 8 + cq);

    const int trow = (lid & 7) + ((lid >> 3) & 1) * 8;
    const int tcol = (lid >> 4) * 8;
    const u32 offA = (u32)(trow * SA_STRIDE + tcol) * 2;
    const u32 offH = (u32)(trow * SH_STRIDE + tcol) * 2;
    const u32 offB = (u32)((wid * 8 + (lid & 7)) * SH_STRIDE + ((lid >> 3) & 1) * 8) * 2;

    const int nTiles = (E + 63) / 64;

    for (int tile = blockIdx.x; tile < nTiles; tile += gridDim.x) {
        const int base = tile * 64;
        __syncthreads();

        // ---- stage indices + A ----
        if (tid < 64) {
            int g = base + tid; if (g >= E) g = E - 1;
            sSS[tid] = senders[g];
            sSR[tid] = recvs[g];
        }
        {
            const int row = tid >> 2, q = tid & 3;
            int ge = base + row; if (ge >= E) ge = E - 1;
            stage_row_quarter(sm, (const float4*)(edgef + (size_t)ge * 64), row, q, EOFF_AH, EOFF_AL);
        }
        __syncthreads();

        // ---- layer 1: acc1[64,128] = A @ We1_e^T (+be1) ----
        // kt outer; all 4 mt A-frags loaded, then term x mt x nt sweep
        // (8 distinct accs between same-acc reuses).
        float acc1[4][2][4];
#pragma unroll
        for (int mt = 0; mt < 4; mt++)
#pragma unroll
            for (int nt = 0; nt < 2; nt++) {
                acc1[mt][nt][0] = bb1[nt].x; acc1[mt][nt][1] = bb1[nt].y;
                acc1[mt][nt][2] = bb1[nt].x; acc1[mt][nt][3] = bb1[nt].y;
            }
#pragma unroll
        for (int kt = 0; kt < 4; kt++) {
            u32 ah[4][4], al[4][4];
#pragma unroll
            for (int mt = 0; mt < 4; mt++) {
                ldsm4(ah[mt], ahb + offA + mt * (16 * SA_STRIDE * 2) + kt * 32);
                ldsm4(al[mt], alb + offA + mt * (16 * SA_STRIDE * 2) + kt * 32);
            }
            // term 0: ah * b1h
#pragma unroll
            for (int mt = 0; mt < 4; mt++) {
                mma_bf(acc1[mt][0], ah[mt], b1h[0][kt]);
                mma_bf(acc1[mt][1], ah[mt], b1h[1][kt]);
            }
            // term 1: ah * b1l
#pragma unroll
            for (int mt = 0; mt < 4; mt++) {
                mma_bf(acc1[mt][0], ah[mt], b1l[0][kt]);
                mma_bf(acc1[mt][1], ah[mt], b1l[1][kt]);
            }
            // term 2: al * b1h
#pragma unroll
            for (int mt = 0; mt < 4; mt++) {
                mma_bf(acc1[mt][0], al[mt], b1h[0][kt]);
                mma_bf(acc1[mt][1], al[mt], b1h[1][kt]);
            }
        }

        // ---- epilogue1: h = relu(acc1 + P1[s] + P2[r]) -> H smem bf16 hi/lo ----
#pragma unroll
        for (int nt = 0; nt < 2; nt++) {
            const int n0 = wid * 16 + nt * 8 + cq;
            float2 p1a[4], p2a[4], p1b[4], p2b[4];
#pragma unroll
            for (int mt = 0; mt < 4; mt++) {
                const int m0 = mt * 16 + nrow, m1 = m0 + 8;
                p1a[mt] = __ldg((const float2*)(g_P + (size_t)sSS[m0] * 384 + n0));
                p2a[mt] = __ldg((const float2*)(g_P + (size_t)sSR[m0] * 384 + 128 + n0));
                p1b[mt] = __ldg((const float2*)(g_P + (size_t)sSS[m1] * 384 + n0));
                p2b[mt] = __ldg((const float2*)(g_P + (size_t)sSR[m1] * 384 + 128 + n0));
            }
#pragma unroll
            for (int mt = 0; mt < 4; mt++) {
                const int m0 = mt * 16 + nrow, m1 = m0 + 8;
                const float x0 = fmaxf(acc1[mt][nt][0] + p1a[mt].x + p2a[mt].x, 0.f);
                const float x1 = fmaxf(acc1[mt][nt][1] + p1a[mt].y + p2a[mt].y, 0.f);
                const float x2 = fmaxf(acc1[mt][nt][2] + p1b[mt].x + p2b[mt].x, 0.f);
                const float x3 = fmaxf(acc1[mt][nt][3] + p1b[mt].y + p2b[mt].y, 0.f);
                const u32 h0 = pack_bf2(x0, x1);
                const u32 h1 = pack_bf2(x2, x3);
                *(u32*)(sm + EOFF_HH + (m0 * SH_STRIDE + n0) * 2) = h0;
                *(u32*)(sm + EOFF_HH + (m1 * SH_STRIDE + n0) * 2) = h1;
                *(u32*)(sm + EOFF_HL + (m0 * SH_STRIDE + n0) * 2) =
                    pack_bf2(x0 - lowf(h0), x1 - highf(h0));
                *(u32*)(sm + EOFF_HL + (m1 * SH_STRIDE + n0) * 2) =
                    pack_bf2(x2 - lowf(h1), x3 - highf(h1));
            }
        }
        __syncthreads();

        // ---- layer 2: acc2[64,64] = h @ We2^T (+be2) ----
        // kt outer; all 4 mt H-frags loaded, term x mt sweep (gap 4).
        float acc2[4][4];
#pragma unroll
        for (int mt = 0; mt < 4; mt++) {
            acc2[mt][0] = bb2.x; acc2[mt][1] = bb2.y;
            acc2[mt][2] = bb2.x; acc2[mt][3] = bb2.y;
        }
#pragma unroll
        for (int kt = 0; kt < 8; kt++) {
            u32 bfh[2], bfl[2];
            ldsm2(bfh, w2h + offB + kt * 32);
            ldsm2(bfl, w2l + offB + kt * 32);
            u32 ah[4][4], al[4][4];
#pragma unroll
            for (int mt = 0; mt < 4; mt++) {
                const u32 rb = mt * (16 * SH_STRIDE * 2) + kt * 32;
                ldsm4(ah[mt], hhb + offH + rb);
                ldsm4(al[mt], hlb + offH + rb);
            }
#pragma unroll
            for (int mt = 0; mt < 4; mt++) mma_bf(acc2[mt], ah[mt], bfh);
#pragma unroll
            for (int mt = 0; mt < 4; mt++) mma_bf(acc2[mt], ah[mt], bfl);
#pragma unroll
            for (int mt = 0; mt < 4; mt++) mma_bf(acc2[mt], al[mt], bfh);
        }

        // ---- epilogue2: stage fp32 -> float4 stores + atomics ----
        {
            const int n2 = wid * 8 + cq;
#pragma unroll
            for (int mt = 0; mt < 4; mt++) {
                const int m0 = mt * 16 + nrow, m1 = m0 + 8;
                *(float2*)(sF + m0 * 68 + n2) = make_float2(acc2[mt][0], acc2[mt][1]);
                *(float2*)(sF + m1 * 68 + n2) = make_float2(acc2[mt][2], acc2[mt][3]);
            }
        }
        __syncthreads();
        {
            const int row = tid >> 2, q = tid & 3;
            const int ge = base + row;
            if (ge < E) {
                const int ridx = sSR[row];
#pragma unroll
                for (int j = 0; j < 4; j++) {
                    const int col = (q + 4 * j) * 4;
                    const float4 v = *(const float4*)(sF + row * 68 + col);
                    *(float4*)(e_out + (size_t)ge * 64 + col) = v;
                    atomicAdd((float4*)(g_agg + (size_t)ridx * 64 + col), v);
                }
            }
        }
    }
}

// ============================================================================
// Node kernel (proven shape): 512 threads, 128-row tiles, 1 CTA/SM.
// n = relu(agg@Wn1_a + Q[node] + bn1) @ Wn2 + bn2
__global__ __launch_bounds__(512, 1)
void node_kernel(const float* __restrict__ Wn1, const float* __restrict__ bn1,
                 const float* __restrict__ Wn2, const float* __restrict__ bn2,
                 float* __restrict__ n_out, int N)
{
    char* sm = smem_raw;
    const u32 smb = smem_u32(sm);
    const u32 ahb = smb + BOFF_AH, alb = smb + BOFF_AL;
    const u32 hhb = smb + BOFF_HH, hlb = smb + BOFF_HL;

    const int tid = threadIdx.x, wid = tid >> 5, lid = tid & 31;
    const int nrow = lid >> 2, cq = (lid & 3) * 2;
    const int mh = wid >> 3;
    const int base = blockIdx.x * 128;

    u32 b1h[4][2], b1l[4][2];
    {
        const int n = wid * 8 + nrow;
#pragma unroll
        for (int kt = 0; kt < 4; kt++)
#pragma unroll
            for (int r = 0; r < 2; r++)
                build_frag(Wn1, 128, n, kt * 16 + cq + r * 8, b1h[kt][r], b1l[kt][r]);
    }
    u32 b2h[8][2], b2l[8][2];
    {
        const int n = (wid & 7) * 8 + nrow;
#pragma unroll
        for (int kt = 0; kt < 8; kt++)
#pragma unroll
            for (int r = 0; r < 2; r++)
                build_frag(Wn2, 64, n, kt * 16 + cq + r * 8, b2h[kt][r], b2l[kt][r]);
    }
    const float2 bb1 = *(const float2*)(bn1 + wid * 8 + cq);
    const float2 bb2 = *(const float2*)(bn2 + (wid & 7) * 8 + cq);

    const int trow = (lid & 7) + ((lid >> 3) & 1) * 8;
    const int tcol = (lid >> 4) * 8;
    const u32 offA = (u32)(trow * SA_STRIDE + tcol) * 2;
    const u32 offH = (u32)(trow * SH_STRIDE + tcol) * 2;

    {
        const int row = tid >> 2, q = tid & 3;
        int g = base + row; if (g >= N) g = N - 1;
        stage_row_quarter(sm, (const float4*)(g_agg + (size_t)g * 64), row, q, BOFF_AH, BOFF_AL);
    }
    __syncthreads();

    float acc1[8][4];
#pragma unroll
    for (int mt = 0; mt < 8; mt++) {
        acc1[mt][0] = bb1.x; acc1[mt][1] = bb1.y;
        acc1[mt][2] = bb1.x; acc1[mt][3] = bb1.y;
    }
#pragma unroll
    for (int mt = 0; mt < 8; mt++) {
        const u32 bh = ahb + offA + mt * (16 * SA_STRIDE * 2);
        const u32 bl = alb + offA + mt * (16 * SA_STRIDE * 2);
#pragma unroll
        for (int kt = 0; kt < 4; kt++) {
            u32 ah[4], al[4];
            ldsm4(ah, bh + kt * 32);
            ldsm4(al, bl + kt * 32);
            mma_bf(acc1[mt], ah, b1h[kt]);
            mma_bf(acc1[mt], ah, b1l[kt]);
            mma_bf(acc1[mt], al, b1h[kt]);
        }
    }

    {
        const int n0 = wid * 8 + cq;
#pragma unroll
        for (int mt = 0; mt < 8; mt++) {
            const int m0 = mt * 16 + nrow, m1 = m0 + 8;
            int g0 = base + m0; if (g0 >= N) g0 = N - 1;
            int g1 = base + m1; if (g1 >= N) g1 = N - 1;
            const float2 qa = __ldg((const float2*)(g_P + (size_t)g0 * 384 + 256 + n0));
            const float2 qb = __ldg((const float2*)(g_P + (size_t)g1 * 384 + 256 + n0));
            const float x0 = fmaxf(acc1[mt][0] + qa.x, 0.f);
            const float x1 = fmaxf(acc1[mt][1] + qa.y, 0.f);
            const float x2 = fmaxf(acc1[mt][2] + qb.x, 0.f);
            const float x3 = fmaxf(acc1[mt][3] + qb.y, 0.f);
            const u32 h0 = pack_bf2(x0, x1);
            const u32 h1 = pack_bf2(x2, x3);
            *(u32*)(sm + BOFF_HH + (m0 * SH_STRIDE + n0) * 2) = h0;
            *(u32*)(sm + BOFF_HH + (m1 * SH_STRIDE + n0) * 2) = h1;
            *(u32*)(sm + BOFF_HL + (m0 * SH_STRIDE + n0) * 2) =
                pack_bf2(x0 - lowf(h0), x1 - highf(h0));
            *(u32*)(sm + BOFF_HL + (m1 * SH_STRIDE + n0) * 2) =
                pack_bf2(x2 - lowf(h1), x3 - highf(h1));
        }
    }
    __syncthreads();

    float acc2[4][4];
#pragma unroll
    for (int mt = 0; mt < 4; mt++) {
        acc2[mt][0] = bb2.x; acc2[mt][1] = bb2.y;
        acc2[mt][2] = bb2.x; acc2[mt][3] = bb2.y;
    }
#pragma unroll
    for (int mt = 0; mt < 4; mt++) {
        const int rowbase = (mh * 4 + mt) * 16;
        const u32 bh = hhb + offH + rowbase * (SH_STRIDE * 2);
        const u32 bl = hlb + offH + rowbase * (SH_STRIDE * 2);
#pragma unroll
        for (int kt = 0; kt < 8; kt++) {
            u32 ah[4], al[4];
            ldsm4(ah, bh + kt * 32);
            ldsm4(al, bl + kt * 32);
            mma_bf(acc2[mt], ah, b2h[kt]);
            mma_bf(acc2[mt], ah, b2l[kt]);
            mma_bf(acc2[mt], al, b2h[kt]);
        }
    }

    {
        const int n2 = (wid & 7) * 8 + cq;
#pragma unroll
        for (int mt = 0; mt < 4; mt++) {
            const int m0 = mh * 64 + mt * 16 + nrow, m1 = m0 + 8;
            const int g0 = base + m0, g1 = base + m1;
            if (g0 < N) *(float2*)(n_out + (size_t)g0 * 64 + n2) =
                            make_float2(acc2[mt][0], acc2[mt][1]);
            if (g1 < N) *(float2*)(n_out + (size_t)g1 * 64 + n2) =
                            make_float2(acc2[mt][2], acc2[mt][3]);
        }
    }
}

// ============================================================================
extern "C" void kernel_launch(void* const* d_in, const int* in_sizes, int n_in,
                              void* d_out, int out_size)
{
    const float* node_feats = (const float*)d_in[0];
    const float* edge_feats = (const float*)d_in[1];
    const float* We1 = (const float*)d_in[2];
    const float* be1 = (const float*)d_in[3];
    const float* We2 = (const float*)d_in[4];
    const float* be2 = (const float*)d_in[5];
    const float* Wn1 = (const float*)d_in[6];
    const float* bn1 = (const float*)d_in[7];
    const float* Wn2 = (const float*)d_in[8];
    const float* bn2 = (const float*)d_in[9];
    const int* senders   = (const int*)d_in[10];
    const int* receivers = (const int*)d_in[11];

    const int N = in_sizes[0] / D;
    const int E = in_sizes[1] / D;

    float* out   = (float*)d_out;
    float* e_out = out;                   // [E, D]
    float* n_out = out + (size_t)E * D;   // [N, D]

    cudaFuncSetAttribute(prep_kernel, cudaFuncAttributeMaxDynamicSharedMemorySize, PPROJ_SMEM);
    cudaFuncSetAttribute(edge_kernel, cudaFuncAttributeMaxDynamicSharedMemorySize, EDGE_SMEM);
    cudaFuncSetAttribute(node_kernel, cudaFuncAttributeMaxDynamicSharedMemorySize, BIG_SMEM);

    int dev = 0, sms = 148;
    cudaGetDevice(&dev);
    cudaDeviceGetAttribute(&sms, cudaDevAttrMultiProcessorCount, dev);

    const int nodeTiles = (N + 127) / 128;
    prep_kernel<<<nodeTiles + ZB, 512, PPROJ_SMEM>>>(node_feats, We1, Wn1, N, nodeTiles);

    edge_kernel<<<2 * sms, 256, EDGE_SMEM>>>(edge_feats, We1, be1, We2, be2,
                                             senders, receivers, e_out, E);

    node_kernel<<<nodeTiles, 512, BIG_SMEM>>>(Wn1, bn1, Wn2, bn2, n_out, N);
}